// round 1
// baseline (speedup 1.0000x reference)
#include <cuda_runtime.h>

typedef unsigned long long u64;

#define Dd   256
#define Hh   4
#define HDh  64
#define Ss   64
#define BM   128
#define TBS  258   // tbuf row stride (floats)
#define ASTR 36    // A staging row stride
#define BSTR 132   // B staging row stride
#define KVSTR 68   // key/val staging row stride
#define SIMSTR 66  // sim buffer row stride

// smem float offsets
#define OFF_TBUF 0
#define OFF_AS   33024
#define OFF_BS   (33024+4608)
#define OFF_SIM  33024            // overlaps As+Bs (used only in attention phase)
#define OFF_KV   (33024+8832)     // 41856
#define OFF_CST  (OFF_KV+4352)    // 46208 : bq(256) bg(256) bo(256) bc1(128) wc2(128)
#define OFF_RED  (OFF_CST+1024)   // 47232 : 128x16
#define OFF_GACC (OFF_RED+2048)   // 49280
#define OFF_CACC (OFF_GACC+128)
#define OFF_A    (OFF_CACC+128)
#define OFF_B2   (OFF_A+128)
#define OFF_RQ   (OFF_B2+128)
#define SMEM_FLOATS (OFF_RQ+128)  // 49920
#define SMEM_BYTES (SMEM_FLOATS*4)

// normalized, transposed keys: [tier][h][d*S + s]
__device__ float g_knT[2][Hh][HDh*Ss];

__global__ void prep_keys(const float* __restrict__ fk, const float* __restrict__ dk) {
    int t = threadIdx.x;          // 256 threads = (h,s)
    int h = t / Ss, s = t % Ss;
    const float* srcs[2] = { fk, dk };
    for (int tier = 0; tier < 2; tier++) {
        const float* src = srcs[tier] + (h * Ss + s) * HDh;
        float ssum = 0.f;
        for (int d2 = 0; d2 < HDh; d2++) { float v = src[d2]; ssum += v * v; }
        float r = 1.0f / (sqrtf(ssum) + 1e-8f);
        for (int d2 = 0; d2 < HDh; d2++)
            g_knT[tier][h][d2 * Ss + s] = src[d2] * r;
    }
}

__device__ __forceinline__ u64 pk2(float v) {
    u64 r; asm("mov.b64 %0, {%1,%2};" : "=l"(r) : "f"(v), "f"(v)); return r;
}
__device__ __forceinline__ void fma2(u64& acc, u64 a, u64 b) {
    asm("fma.rn.f32x2 %0, %1, %2, %0;" : "+l"(acc) : "l"(a), "l"(b));
}
__device__ __forceinline__ float2 unp(u64 v) {
    float2 f; asm("mov.b64 {%0,%1}, %2;" : "=f"(f.x), "=f"(f.y) : "l"(v)); return f;
}

// C[128 x 128] = A[128 x 256] @ W[n0..n0+127, 0..255]^T ; acc = 8x4 f32x2 per thread
__device__ __forceinline__ void gemm_256xN(
    const float* __restrict__ Ag, const float* __restrict__ W, int n0,
    float* As, float* Bs, u64 acc[8][4], int tid, int tx, int ty)
{
    #pragma unroll
    for (int i = 0; i < 8; i++)
        #pragma unroll
        for (int j = 0; j < 4; j++) acc[i][j] = 0ull;

    for (int kt = 0; kt < 8; kt++) {
        const int k0 = kt * 32;
        #pragma unroll
        for (int r = 0; r < 4; r++) {          // stage A tile 128x32 (row-major)
            int lin = tid + r * 256;
            int m = lin >> 3, q = lin & 7;
            float4 v = *(const float4*)(Ag + m * Dd + k0 + q * 4);
            *(float4*)(As + m * ASTR + q * 4) = v;
        }
        #pragma unroll
        for (int r = 0; r < 4; r++) {          // stage B tile transposed: Bs[k][n] = W[n0+n][k0+k]
            int lin = tid + r * 256;
            int n = lin >> 3, q = lin & 7;
            float4 v = *(const float4*)(W + (n0 + n) * Dd + k0 + q * 4);
            Bs[(q * 4 + 0) * BSTR + n] = v.x;
            Bs[(q * 4 + 1) * BSTR + n] = v.y;
            Bs[(q * 4 + 2) * BSTR + n] = v.z;
            Bs[(q * 4 + 3) * BSTR + n] = v.w;
        }
        __syncthreads();
        #pragma unroll
        for (int kk = 0; kk < 32; kk += 4) {
            float4 a4[8];
            #pragma unroll
            for (int i = 0; i < 8; i++)
                a4[i] = *(const float4*)(As + (ty * 8 + i) * ASTR + kk);
            #pragma unroll
            for (int u = 0; u < 4; u++) {
                const float* brow = Bs + (kk + u) * BSTR + tx * 8;
                u64 b0 = *(const u64*)(brow + 0);
                u64 b1 = *(const u64*)(brow + 2);
                u64 b2 = *(const u64*)(brow + 4);
                u64 b3 = *(const u64*)(brow + 6);
                #pragma unroll
                for (int i = 0; i < 8; i++) {
                    float av = (u == 0) ? a4[i].x : (u == 1) ? a4[i].y : (u == 2) ? a4[i].z : a4[i].w;
                    u64 aa = pk2(av);
                    fma2(acc[i][0], aa, b0);
                    fma2(acc[i][1], aa, b1);
                    fma2(acc[i][2], aa, b2);
                    fma2(acc[i][3], aa, b3);
                }
            }
        }
        __syncthreads();
    }
}

// C[128 x 64] (+)= A[128 rows, cols acb..acb+63 of Asm] @ kvS[64 x 64]; acc = 8x2 f32x2
__device__ __forceinline__ void gemm_attn(
    const float* __restrict__ Asm, int astride, int acb,
    const float* __restrict__ kvS, u64 acc[8][2], int tx, int ty, bool zero)
{
    if (zero) {
        #pragma unroll
        for (int i = 0; i < 8; i++) { acc[i][0] = 0ull; acc[i][1] = 0ull; }
    }
    #pragma unroll 4
    for (int kk = 0; kk < 64; kk += 2) {
        float2 a2[8];
        #pragma unroll
        for (int i = 0; i < 8; i++)
            a2[i] = *(const float2*)(Asm + (ty * 8 + i) * astride + acb + kk);
        #pragma unroll
        for (int u = 0; u < 2; u++) {
            const float* brow = kvS + (kk + u) * KVSTR + tx * 4;
            u64 b0 = *(const u64*)(brow);
            u64 b1 = *(const u64*)(brow + 2);
            #pragma unroll
            for (int i = 0; i < 8; i++) {
                u64 aa = pk2(u ? a2[i].y : a2[i].x);
                fma2(acc[i][0], aa, b0);
                fma2(acc[i][1], aa, b1);
            }
        }
    }
}

__device__ __forceinline__ void stage_kv(float* kv, const float* __restrict__ src, int tid) {
    #pragma unroll
    for (int r = 0; r < 4; r++) {
        int lin = tid + r * 256;
        int row = lin >> 4, q = lin & 15;
        float4 v = *(const float4*)(src + row * 64 + q * 4);
        *(float4*)(kv + row * KVSTR + q * 4) = v;
    }
}

__device__ __forceinline__ void softmax_row(float* row, float scale) {
    float mx = -1e30f;
    for (int s2 = 0; s2 < 64; s2++) mx = fmaxf(mx, row[s2]);
    float sum = 0.f;
    for (int s2 = 0; s2 < 64; s2++) { float e = expf(row[s2] - mx); row[s2] = e; sum += e; }
    float inv = scale / sum;
    for (int s2 = 0; s2 < 64; s2++) row[s2] *= inv;
}

__global__ void __launch_bounds__(256, 1) miras_main(
    const float* __restrict__ query, const float* __restrict__ context,
    const float* __restrict__ fvals, const float* __restrict__ dvals,
    const float* __restrict__ Wq, const float* __restrict__ bq,
    const float* __restrict__ Wg, const float* __restrict__ bg,
    const float* __restrict__ Wc1, const float* __restrict__ bc1,
    const float* __restrict__ Wc2, const float* __restrict__ bc2,
    const float* __restrict__ Wo, const float* __restrict__ bo,
    const float* __restrict__ mixl,
    float* __restrict__ out)
{
    extern __shared__ float sm[];
    float* tbuf = sm + OFF_TBUF;
    float* As   = sm + OFF_AS;
    float* Bs   = sm + OFF_BS;
    float* simb = sm + OFF_SIM;
    float* kv   = sm + OFF_KV;
    float* cst  = sm + OFF_CST;
    float* red  = sm + OFF_RED;
    float* gaccS = sm + OFF_GACC;
    float* caccS = sm + OFF_CACC;
    float* aS   = sm + OFF_A;
    float* b2S  = sm + OFF_B2;
    float* rqS  = sm + OFF_RQ;

    const int tid = threadIdx.x;
    const int tx = tid & 15, ty = tid >> 4;
    const int m0 = blockIdx.x * BM;

    // load small constants into smem
    cst[tid]       = bq[tid];
    cst[256 + tid] = bg[tid];
    cst[512 + tid] = bo[tid];
    if (tid < 128) { cst[768 + tid] = bc1[tid]; cst[896 + tid] = Wc2[tid]; }
    const float mix_logit = mixl[0];
    const float bc2v = bc2[0];
    __syncthreads();

    u64 acc[8][4];

    // ---------- Phase A: gate (Wg) + conf (Wc1) from context ----------
    float gpart[8];
    #pragma unroll
    for (int i = 0; i < 8; i++) gpart[i] = 0.f;

    for (int np = 0; np < 2; np++) {
        gemm_256xN(context + (size_t)m0 * Dd, Wg, np * 128, As, Bs, acc, tid, tx, ty);
        #pragma unroll
        for (int i = 0; i < 8; i++) {
            float s = 0.f;
            #pragma unroll
            for (int j = 0; j < 4; j++) {
                float2 v = unp(acc[i][j]);
                int n = np * 128 + tx * 8 + j * 2;
                s += tanhf(v.x + cst[256 + n]) + tanhf(v.y + cst[256 + n + 1]);
            }
            gpart[i] += s;
        }
    }

    gemm_256xN(context + (size_t)m0 * Dd, Wc1, 0, As, Bs, acc, tid, tx, ty);
    float cpart[8];
    #pragma unroll
    for (int i = 0; i < 8; i++) {
        float s = 0.f;
        #pragma unroll
        for (int j = 0; j < 4; j++) {
            float2 v = unp(acc[i][j]);
            int n = tx * 8 + j * 2;
            s += tanhf(v.x + cst[768 + n]) * cst[896 + n]
               + tanhf(v.y + cst[768 + n + 1]) * cst[896 + n + 1];
        }
        cpart[i] = s;
    }

    // deterministic reductions
    #pragma unroll
    for (int i = 0; i < 8; i++) red[(ty * 8 + i) * 16 + tx] = gpart[i];
    __syncthreads();
    if (tid < 128) {
        float s = 0.f;
        for (int t16 = 0; t16 < 16; t16++) s += red[tid * 16 + t16];
        gaccS[tid] = s;
    }
    __syncthreads();
    #pragma unroll
    for (int i = 0; i < 8; i++) red[(ty * 8 + i) * 16 + tx] = cpart[i];
    __syncthreads();
    if (tid < 128) {
        float s = 0.f;
        for (int t16 = 0; t16 < 16; t16++) s += red[tid * 16 + t16];
        caccS[tid] = s;
        float gate = gaccS[tid] * (1.0f / 256.0f);
        float mixv = 1.0f / (1.0f + expf(-(mix_logit + gate)));
        float conf = 1.0f / (1.0f + expf(-(s + bc2v)));
        aS[tid] = mixv * conf;
        b2S[tid] = (1.0f - mixv) * conf;
    }
    __syncthreads();

    // ---------- Phase B: Q = query @ Wq^T + bq -> tbuf ----------
    for (int np = 0; np < 2; np++) {
        gemm_256xN(query + (size_t)m0 * Dd, Wq, np * 128, As, Bs, acc, tid, tx, ty);
        #pragma unroll
        for (int i = 0; i < 8; i++) {
            int row = ty * 8 + i;
            #pragma unroll
            for (int j = 0; j < 4; j++) {
                float2 v = unp(acc[i][j]);
                int n = np * 128 + tx * 8 + j * 2;
                tbuf[row * TBS + n]     = v.x + cst[n];
                tbuf[row * TBS + n + 1] = v.y + cst[n + 1];
            }
        }
        __syncthreads();
    }

    // ---------- Phase C: dual-tier cosine attention, in-place t over Q ----------
    u64 accS[8][2], accT[8][2];
    for (int h = 0; h < Hh; h++) {
        stage_kv(kv, &g_knT[0][h][0], tid);
        if (tid < 128) {
            const float* qr = tbuf + tid * TBS + h * 64;
            float ssum = 0.f;
            for (int d2 = 0; d2 < 64; d2++) { float v = qr[d2]; ssum += v * v; }
            rqS[tid] = 1.0f / (sqrtf(ssum) + 1e-8f);
        }
        __syncthreads();

        // sim fast = Q_h @ knT_f, scaled by 1/(||q||+eps)
        gemm_attn(tbuf, TBS, h * 64, kv, accS, tx, ty, true);
        #pragma unroll
        for (int i = 0; i < 8; i++) {
            float r = rqS[ty * 8 + i];
            float2 v0 = unp(accS[i][0]), v1 = unp(accS[i][1]);
            float* srow = simb + (ty * 8 + i) * SIMSTR + tx * 4;
            srow[0] = v0.x * r; srow[1] = v0.y * r; srow[2] = v1.x * r; srow[3] = v1.y * r;
        }
        __syncthreads();

        stage_kv(kv, fvals + h * Ss * HDh, tid);
        if (tid < 128) softmax_row(simb + tid * SIMSTR, aS[tid]);   // attnF * conf*mix
        __syncthreads();

        gemm_attn(simb, SIMSTR, 0, kv, accT, tx, ty, true);         // t += attnF' @ fvals
        __syncthreads();

        stage_kv(kv, &g_knT[1][h][0], tid);
        __syncthreads();

        gemm_attn(tbuf, TBS, h * 64, kv, accS, tx, ty, true);       // sim deep
        #pragma unroll
        for (int i = 0; i < 8; i++) {
            float r = rqS[ty * 8 + i];
            float2 v0 = unp(accS[i][0]), v1 = unp(accS[i][1]);
            float* srow = simb + (ty * 8 + i) * SIMSTR + tx * 4;
            srow[0] = v0.x * r; srow[1] = v0.y * r; srow[2] = v1.x * r; srow[3] = v1.y * r;
        }
        __syncthreads();

        stage_kv(kv, dvals + h * Ss * HDh, tid);
        if (tid < 128) softmax_row(simb + tid * SIMSTR, b2S[tid]);  // attnD * conf*(1-mix)
        __syncthreads();

        gemm_attn(simb, SIMSTR, 0, kv, accT, tx, ty, false);        // t += attnD' @ dvals

        #pragma unroll
        for (int i = 0; i < 8; i++) {                               // overwrite Q_h with t_h
            float2 v0 = unp(accT[i][0]), v1 = unp(accT[i][1]);
            float* trow = tbuf + (ty * 8 + i) * TBS + h * 64 + tx * 4;
            trow[0] = v0.x; trow[1] = v0.y; trow[2] = v1.x; trow[3] = v1.y;
        }
        __syncthreads();
    }

    // ---------- Phase D: out = t @ Wo^T + bo ----------
    for (int np = 0; np < 2; np++) {
        #pragma unroll
        for (int i = 0; i < 8; i++)
            #pragma unroll
            for (int j = 0; j < 4; j++) acc[i][j] = 0ull;

        for (int kt = 0; kt < 8; kt++) {
            const int k0 = kt * 32;
            #pragma unroll
            for (int r = 0; r < 4; r++) {
                int lin = tid + r * 256;
                int n = lin >> 3, q = lin & 7;
                float4 v = *(const float4*)(Wo + (np * 128 + n) * Dd + k0 + q * 4);
                Bs[(q * 4 + 0) * BSTR + n] = v.x;
                Bs[(q * 4 + 1) * BSTR + n] = v.y;
                Bs[(q * 4 + 2) * BSTR + n] = v.z;
                Bs[(q * 4 + 3) * BSTR + n] = v.w;
            }
            __syncthreads();
            #pragma unroll
            for (int kk = 0; kk < 32; kk += 2) {
                float2 a2[8];
                #pragma unroll
                for (int i = 0; i < 8; i++)
                    a2[i] = *(const float2*)(tbuf + (ty * 8 + i) * TBS + k0 + kk);
                #pragma unroll
                for (int u = 0; u < 2; u++) {
                    const float* brow = Bs + (kk + u) * BSTR + tx * 8;
                    u64 b0 = *(const u64*)(brow + 0);
                    u64 b1 = *(const u64*)(brow + 2);
                    u64 b2 = *(const u64*)(brow + 4);
                    u64 b3 = *(const u64*)(brow + 6);
                    #pragma unroll
                    for (int i = 0; i < 8; i++) {
                        u64 aa = pk2(u ? a2[i].y : a2[i].x);
                        fma2(acc[i][0], aa, b0);
                        fma2(acc[i][1], aa, b1);
                        fma2(acc[i][2], aa, b2);
                        fma2(acc[i][3], aa, b3);
                    }
                }
            }
            __syncthreads();
        }
        #pragma unroll
        for (int i = 0; i < 8; i++) {
            int row = m0 + ty * 8 + i;
            float2 v0 = unp(acc[i][0]), v1 = unp(acc[i][1]);
            float2 v2 = unp(acc[i][2]), v3 = unp(acc[i][3]);
            int n = np * 128 + tx * 8;
            float4 o0 = make_float4(v0.x + cst[512 + n],     v0.y + cst[512 + n + 1],
                                    v1.x + cst[512 + n + 2], v1.y + cst[512 + n + 3]);
            float4 o1 = make_float4(v2.x + cst[512 + n + 4], v2.y + cst[512 + n + 5],
                                    v3.x + cst[512 + n + 6], v3.y + cst[512 + n + 7]);
            *(float4*)(out + (size_t)row * Dd + n)     = o0;
            *(float4*)(out + (size_t)row * Dd + n + 4) = o1;
        }
    }
}

extern "C" void kernel_launch(void* const* d_in, const int* in_sizes, int n_in,
                              void* d_out, int out_size) {
    (void)in_sizes; (void)n_in; (void)out_size;
    const float* query   = (const float*)d_in[0];
    const float* context = (const float*)d_in[1];
    const float* fk  = (const float*)d_in[2];
    const float* fv  = (const float*)d_in[3];
    const float* dk  = (const float*)d_in[4];
    const float* dv  = (const float*)d_in[5];
    const float* Wq  = (const float*)d_in[6];
    const float* bq  = (const float*)d_in[7];
    const float* Wg  = (const float*)d_in[8];
    const float* bg  = (const float*)d_in[9];
    const float* Wc1 = (const float*)d_in[10];
    const float* bc1 = (const float*)d_in[11];
    const float* Wc2 = (const float*)d_in[12];
    const float* bc2 = (const float*)d_in[13];
    const float* Wo  = (const float*)d_in[14];
    const float* bo  = (const float*)d_in[15];
    const float* mixl = (const float*)d_in[18];
    float* out = (float*)d_out;

    cudaFuncSetAttribute(miras_main, cudaFuncAttributeMaxDynamicSharedMemorySize, SMEM_BYTES);

    prep_keys<<<1, 256>>>(fk, dk);
    miras_main<<<512, 256, SMEM_BYTES>>>(query, context, fv, dv,
                                         Wq, bq, Wg, bg, Wc1, bc1, Wc2, bc2,
                                         Wo, bo, mixl, out);
}